// round 12
// baseline (speedup 1.0000x reference)
#include <cuda_runtime.h>
#include <math.h>

#define BB     32
#define SS     256
#define ISZ    1024
#define OSZ    1024
#define N4     4096
#define EPSF   1e-5f
#define NBLK   128
#define NTHR   256
#define CHUNK  256                 // k-extent per staged chunk
#define NCH    4                   // 1024 / 256

typedef unsigned long long ull;

// Scratch (device globals -- no runtime allocation allowed)
__device__ float    g_xproj[BB * SS * N4];    // x @ W_x + b for all timesteps
__device__ float    g_h[BB * OSZ];            // hidden state (global, cross-block)
__device__ float    g_part[2][BB][NBLK];      // LN partial sums [stat][row][block]
__device__ unsigned g_bar;                    // grid barrier counter

// ---------------------------------------------------------------------------
// Packed f32x2 helpers (FFMA2 -- exact fp32 x2 per instruction)
// ---------------------------------------------------------------------------
__device__ __forceinline__ ull ffma2(ull a, ull b, ull c) {
    ull d;
    asm("fma.rn.f32x2 %0, %1, %2, %3;" : "=l"(d) : "l"(a), "l"(b), "l"(c));
    return d;
}
__device__ __forceinline__ ull pack2(float lo, float hi) {
    ull d;
    asm("mov.b64 %0, {%1, %2};" : "=l"(d) : "f"(lo), "f"(hi));
    return d;
}
__device__ __forceinline__ float2 unpack2(ull v) {
    float2 r;
    asm("mov.b64 {%0, %1}, %2;" : "=f"(r.x), "=f"(r.y) : "l"(v));
    return r;
}

// ---------------------------------------------------------------------------
// Init: h from init_hx (broadcast over batch), reset barrier.
// MUST cover BB*OSZ = 32768 elements: h persists across graph replays.
// ---------------------------------------------------------------------------
__global__ void init_state(const float* __restrict__ init_hx) {
    int j = blockIdx.x * blockDim.x + threadIdx.x;
    if (j == 0) g_bar = 0;
    if (j < BB * OSZ) g_h[j] = init_hx[j & (OSZ - 1)];
}

// ---------------------------------------------------------------------------
// xproj[row, n] = b[n] + sum_k x[row, k] * W[k, n]
// EXACT R6 form (measured best). FFMA2 over k-pairs.
// Block (32,8): thread = 4 rows x 4 cols. Grid (32, 256).
// ---------------------------------------------------------------------------
__global__ void xproj_kernel(const float* __restrict__ x,
                             const float* __restrict__ W,
                             const float* __restrict__ bias) {
    const int tx = threadIdx.x, ty = threadIdx.y;
    const int col0 = (blockIdx.x * 32 + tx) * 4;
    const int row0 = blockIdx.y * 32 + ty * 4;

    ull acc2[4][4];
    #pragma unroll
    for (int r = 0; r < 4; r++)
        #pragma unroll
        for (int c = 0; c < 4; c++) acc2[r][c] = 0ull;

    const float* xp = x + (size_t)row0 * ISZ;

    #pragma unroll 2
    for (int k = 0; k < ISZ; k += 4) {
        float4 w0 = *(const float4*)(W + (size_t)(k + 0) * N4 + col0);
        float4 w1 = *(const float4*)(W + (size_t)(k + 1) * N4 + col0);
        float4 w2 = *(const float4*)(W + (size_t)(k + 2) * N4 + col0);
        float4 w3 = *(const float4*)(W + (size_t)(k + 3) * N4 + col0);

        ull wp01[4], wp23[4];
        wp01[0] = pack2(w0.x, w1.x); wp01[1] = pack2(w0.y, w1.y);
        wp01[2] = pack2(w0.z, w1.z); wp01[3] = pack2(w0.w, w1.w);
        wp23[0] = pack2(w2.x, w3.x); wp23[1] = pack2(w2.y, w3.y);
        wp23[2] = pack2(w2.z, w3.z); wp23[3] = pack2(w2.w, w3.w);

        #pragma unroll
        for (int r = 0; r < 4; r++) {
            ulonglong2 xv = __ldg((const ulonglong2*)(xp + (size_t)r * ISZ + k));
            #pragma unroll
            for (int c = 0; c < 4; c++) {
                acc2[r][c] = ffma2(xv.x, wp01[c], acc2[r][c]);
                acc2[r][c] = ffma2(xv.y, wp23[c], acc2[r][c]);
            }
        }
    }

    float4 bv = *(const float4*)(bias + col0);
    #pragma unroll
    for (int r = 0; r < 4; r++) {
        float2 a0 = unpack2(acc2[r][0]);
        float2 a1 = unpack2(acc2[r][1]);
        float2 a2 = unpack2(acc2[r][2]);
        float2 a3 = unpack2(acc2[r][3]);
        float4 o;
        o.x = a0.x + a0.y + bv.x;
        o.y = a1.x + a1.y + bv.y;
        o.z = a2.x + a2.y + bv.z;
        o.w = a3.x + a3.y + bv.w;
        *(float4*)(g_xproj + (size_t)(row0 + r) * N4 + col0) = o;
    }
}

// ---------------------------------------------------------------------------
// Software grid barrier -- atomic counter on ONE hot L2 line (measured
// fastest vs distributed flags and one-sided chunk counters)
// ---------------------------------------------------------------------------
__device__ __forceinline__ void gsync(unsigned target) {
    __syncthreads();
    if (threadIdx.x == 0) {
        __threadfence();
        atomicAdd(&g_bar, 1u);
        while (*(volatile unsigned*)&g_bar < target) { }
        __threadfence();
    }
    __syncthreads();
}

// ---------------------------------------------------------------------------
// Persistent LSTM recurrence -- ROW-ownership GEMM (no cross-warp reduction).
// Block `blk` owns output cols {g*1024 + blk*8 + q}.
// Warp ty owns batch rows b0=ty*4..b0+3 over the FULL k range:
//   8 f32x2 accumulators (2 ILP chains x 4 rows), W read per-warp from SMEM
//   (8x redundant but +1792 LDS beats the 16K-op k-reduction it replaces).
// ---------------------------------------------------------------------------
__global__ void __launch_bounds__(NTHR, 1)
lstm_persist(const float* __restrict__ W,
             const float* __restrict__ gamma,
             const float* __restrict__ beta,
             const float* __restrict__ init_cx,
             float* __restrict__ out) {
    extern __shared__ float smem[];
    float4* __restrict__ Wsf4 = (float4*)smem;               // [8192] float4
    float4* __restrict__ Hbuf = (float4*)(smem + 32768);     // [2][2048] float4
    __shared__ float c_sm[BB * 8];

    const int tid = threadIdx.x;
    const int tx  = tid & 31, ty = tid >> 5;
    const int blk = blockIdx.x;
    const int g   = tx >> 3, q = tx & 7;
    const int gcol = g * OSZ + blk * 8 + q;
    const int b0  = ty * 4;

    // Preload W_h slice into float4 layout: smem[(k>>2)*128 + c*4 + (k&3)]
    for (int idx = tid; idx < ISZ * 32; idx += NTHR) {
        int k = idx >> 5, c = idx & 31;
        int col = (c >> 3) * OSZ + blk * 8 + (c & 7);
        smem[(k >> 2) * 128 + c * 4 + (k & 3)] = W[(size_t)(ISZ + k) * N4 + col];
    }
    if (tid < BB * 8)
        c_sm[tid] = init_cx[blk * 8 + (tid & 7)];

    const float gam = gamma[gcol];
    const float bet = beta[gcol];

    // Cooperative-load source indices (8 float4 per chunk per thread)
    int ld_r[8], ld_j[8];
    #pragma unroll
    for (int u = 0; u < 8; u++) {
        int i = u * NTHR + tid;
        ld_r[u] = i >> 6;
        ld_j[u] = i & 63;
    }
    __syncthreads();

    unsigned nsync = 0;

    // Prefetch xproj for t=0
    float px[4];
    #pragma unroll
    for (int r = 0; r < 4; r++)
        px[r] = __ldcg(&g_xproj[((size_t)(b0 + r) * SS + 0) * N4 + gcol]);

    for (int t = 0; t < SS; t++) {
        float cur[4];
        #pragma unroll
        for (int r = 0; r < 4; r++) cur[r] = px[r];
        if (t + 1 < SS) {
            #pragma unroll
            for (int r = 0; r < 4; r++)
                px[r] = __ldcg(&g_xproj[((size_t)(b0 + r) * SS + t + 1) * N4 + gcol]);
        }

        // ---- stage chunk 0 of h ----
        {
            float4 ld[8];
            #pragma unroll
            for (int u = 0; u < 8; u++)
                ld[u] = __ldcg((const float4*)(g_h + (size_t)ld_r[u] * OSZ + ld_j[u] * 4));
            #pragma unroll
            for (int u = 0; u < 8; u++)
                Hbuf[u * NTHR + tid] = ld[u];
        }
        __syncthreads();

        // ---- recurrent GEMM: warp ty owns rows b0..b0+3 over full k ----
        ull accA[4], accB[4];
        #pragma unroll
        for (int r = 0; r < 4; r++) { accA[r] = 0ull; accB[r] = 0ull; }

        #pragma unroll 1
        for (int c = 0; c < NCH; c++) {
            float4 ldn[8];
            if (c < NCH - 1) {
                const int k0n = (c + 1) * CHUNK;
                #pragma unroll
                for (int u = 0; u < 8; u++)
                    ldn[u] = __ldcg((const float4*)(g_h + (size_t)ld_r[u] * OSZ + k0n + ld_j[u] * 4));
            }

            const float4* __restrict__ hb = Hbuf + (c & 1) * 2048;
            const ulonglong2* __restrict__ wp =
                (const ulonglong2*)Wsf4 + (size_t)(c * 64) * 32 + tx;

            #pragma unroll 4
            for (int j = 0; j < 64; j++) {
                ulonglong2 wv = wp[j * 32];             // {w[k],w[k+1]},{w[k+2],w[k+3]}
                #pragma unroll
                for (int r = 0; r < 4; r++) {
                    ulonglong2 hv =
                        *(const ulonglong2*)(hb + ((b0 + r) * 64 + j));  // broadcast
                    accA[r] = ffma2(hv.x, wv.x, accA[r]);
                    accB[r] = ffma2(hv.y, wv.y, accB[r]);
                }
            }

            if (c < NCH - 1) {
                float4* __restrict__ hn = Hbuf + ((c + 1) & 1) * 2048;
                #pragma unroll
                for (int u = 0; u < 8; u++)
                    hn[u * NTHR + tid] = ldn[u];
                __syncthreads();
            }
        }

        float acc[4];
        #pragma unroll
        for (int r = 0; r < 4; r++) {
            float2 a = unpack2(accA[r]);
            float2 b = unpack2(accB[r]);
            acc[r] = ((a.x + a.y) + (b.x + b.y)) + cur[r];
        }

        // ---- LN partial sums over this block's 32 columns, per row ----
        float s[4], ss[4];
        #pragma unroll
        for (int r = 0; r < 4; r++) { s[r] = acc[r]; ss[r] = acc[r] * acc[r]; }
        #pragma unroll
        for (int o = 16; o > 0; o >>= 1) {
            #pragma unroll
            for (int r = 0; r < 4; r++) {
                s[r]  += __shfl_xor_sync(0xffffffffu, s[r],  o);
                ss[r] += __shfl_xor_sync(0xffffffffu, ss[r], o);
            }
        }
        if (tx == 0) {
            #pragma unroll
            for (int r = 0; r < 4; r++) {
                __stcg(&g_part[0][b0 + r][blk], s[r]);
                __stcg(&g_part[1][b0 + r][blk], ss[r]);
            }
        }

        gsync(++nsync * NBLK);

        // ---- aggregate stats (deterministic): warp ty handles rows b0..b0+3 ----
        float mean[4], rstd[4];
        #pragma unroll
        for (int r = 0; r < 4; r++) {
            int row = b0 + r;
            float4 sv = __ldcg((const float4*)&g_part[0][row][tx * 4]);
            float4 qv = __ldcg((const float4*)&g_part[1][row][tx * 4]);
            float sl = (sv.x + sv.y) + (sv.z + sv.w);
            float ql = (qv.x + qv.y) + (qv.z + qv.w);
            #pragma unroll
            for (int o = 16; o > 0; o >>= 1) {
                sl += __shfl_xor_sync(0xffffffffu, sl, o);
                ql += __shfl_xor_sync(0xffffffffu, ql, o);
            }
            float m = sl * (1.0f / N4);
            mean[r] = m;
            rstd[r] = rsqrtf(ql * (1.0f / N4) - m * m + EPSF);
        }

        // ---- LN + gates. Gates of index i sit in lanes q, q+8, q+16, q+24 ----
        #pragma unroll
        for (int r = 0; r < 4; r++) {
            float v = (acc[r] - mean[r]) * rstd[r] * gam + bet;
            float a0 = __shfl_sync(0xffffffffu, v, q);        // ig
            float a1 = __shfl_sync(0xffffffffu, v, q + 8);    // fg
            float a2 = __shfl_sync(0xffffffffu, v, q + 16);   // hidden
            float a3 = __shfl_sync(0xffffffffu, v, q + 24);   // og
            if (g == 0) {
                int b = b0 + r;
                int i = blk * 8 + q;
                float si = 1.0f / (1.0f + expf(-a0));
                float sf = 1.0f / (1.0f + expf(-a1));
                float so = 1.0f / (1.0f + expf(-a3));
                float co = c_sm[b * 8 + q];
                float cn = sf * co + si * tanhf(a2);
                float h  = so * cn;
                c_sm[b * 8 + q] = cn;
                __stcg(&g_h[(size_t)b * OSZ + i], h);
                out[((size_t)b * SS + t) * OSZ + i] = h;
            }
        }

        gsync(++nsync * NBLK);
    }
}

// ---------------------------------------------------------------------------
// Inputs (metadata order): x, W, b, gamma, beta, init_hx, init_cx
// ---------------------------------------------------------------------------
extern "C" void kernel_launch(void* const* d_in, const int* in_sizes, int n_in,
                              void* d_out, int out_size) {
    const float* x       = (const float*)d_in[0];
    const float* W       = (const float*)d_in[1];
    const float* bias    = (const float*)d_in[2];
    const float* gamma   = (const float*)d_in[3];
    const float* beta    = (const float*)d_in[4];
    const float* init_hx = (const float*)d_in[5];
    const float* init_cx = (const float*)d_in[6];
    float* out = (float*)d_out;

    // 128 blocks: must cover BB*OSZ = 32768 h elements
    init_state<<<(BB * OSZ + 255) / 256, 256>>>(init_hx);

    dim3 blk(32, 8);
    xproj_kernel<<<dim3(32, 256), blk>>>(x, W, bias);

    cudaFuncSetAttribute(lstm_persist,
                         cudaFuncAttributeMaxDynamicSharedMemorySize, 196608);
    lstm_persist<<<NBLK, NTHR, 196608>>>(W, gamma, beta, init_cx, out);
}

// round 13
// speedup vs baseline: 1.0912x; 1.0912x over previous
#include <cuda_runtime.h>
#include <math.h>

#define BB     32
#define SS     256
#define ISZ    1024
#define OSZ    1024
#define N4     4096
#define EPSF   1e-5f
#define NBLK   128
#define NTHR   256
#define CHUNK  256                 // k-extent per staged chunk
#define NCH    4                   // 1024 / 256

typedef unsigned long long ull;

// Scratch (device globals -- no runtime allocation allowed)
__device__ float    g_xproj[BB * SS * N4];    // x @ W_x + b for all timesteps
__device__ float    g_wpk[ISZ * N4];          // W_x k-pair-interleaved: [k/2][col][2]
__device__ float    g_h[BB * OSZ];            // hidden state (global, cross-block)
__device__ float    g_part[2][BB][NBLK];      // LN partial sums [stat][row][block]
__device__ unsigned g_bar;                    // grid barrier counter

// ---------------------------------------------------------------------------
// Packed f32x2 helpers (FFMA2 -- exact fp32 x2 per instruction)
// ---------------------------------------------------------------------------
__device__ __forceinline__ ull ffma2(ull a, ull b, ull c) {
    ull d;
    asm("fma.rn.f32x2 %0, %1, %2, %3;" : "=l"(d) : "l"(a), "l"(b), "l"(c));
    return d;
}
__device__ __forceinline__ float2 unpack2(ull v) {
    float2 r;
    asm("mov.b64 {%0, %1}, %2;" : "=f"(r.x), "=f"(r.y) : "l"(v));
    return r;
}

// ---------------------------------------------------------------------------
// Init: h from init_hx (broadcast over batch), reset barrier.
// MUST cover BB*OSZ = 32768 elements: h persists across graph replays.
// ---------------------------------------------------------------------------
__global__ void init_state(const float* __restrict__ init_hx) {
    int j = blockIdx.x * blockDim.x + threadIdx.x;
    if (j == 0) g_bar = 0;
    if (j < BB * OSZ) g_h[j] = init_hx[j & (OSZ - 1)];
}

// ---------------------------------------------------------------------------
// Prepack W_x into k-pair-interleaved layout:
//   g_wpk[p*8192 + col*2 + par] = W[(2p+par)*N4 + col]
// Thread p,col reads two coalesced W rows, writes one coalesced float2.
// ---------------------------------------------------------------------------
__global__ void prepack_w(const float* __restrict__ W) {
    int idx = blockIdx.x * blockDim.x + threadIdx.x;    // [0, 512*4096)
    int p   = idx >> 12;           // k-pair index
    int col = idx & (N4 - 1);
    float2 v;
    v.x = W[(size_t)(2 * p + 0) * N4 + col];
    v.y = W[(size_t)(2 * p + 1) * N4 + col];
    *(float2*)(g_wpk + (size_t)p * (2 * N4) + col * 2) = v;
}

// ---------------------------------------------------------------------------
// xproj[row, n] = b[n] + sum_k x[row, k] * W[k, n]
// FFMA2 over k-pairs with PREPACKED W: zero pack MOVs in the hot loop.
// x ulonglong2 loads give natural {x[k],x[k+1]} pairs; W pairs come
// straight from g_wpk via LDG.128.
// Block (32,8): thread = 4 rows x 4 cols. Grid (32, 256).
// ---------------------------------------------------------------------------
__global__ void xproj_kernel(const float* __restrict__ x,
                             const float* __restrict__ bias) {
    const int tx = threadIdx.x, ty = threadIdx.y;
    const int col0 = (blockIdx.x * 32 + tx) * 4;
    const int row0 = blockIdx.y * 32 + ty * 4;

    ull acc2[4][4];
    #pragma unroll
    for (int r = 0; r < 4; r++)
        #pragma unroll
        for (int c = 0; c < 4; c++) acc2[r][c] = 0ull;

    const float* xp = x + (size_t)row0 * ISZ;
    const float* wb = g_wpk + (size_t)col0 * 2;   // pair-row stride = 8192 floats

    #pragma unroll 2
    for (int k = 0; k < ISZ; k += 4) {
        const ulonglong2* w01 = (const ulonglong2*)(wb + (size_t)(k >> 1) * (2 * N4));
        const ulonglong2* w23 = (const ulonglong2*)(wb + (size_t)((k >> 1) + 1) * (2 * N4));
        ulonglong2 wa = w01[0];   // {pair(c0), pair(c1)} for k,k+1
        ulonglong2 wbv = w01[1];  // {pair(c2), pair(c3)} for k,k+1
        ulonglong2 wc = w23[0];   // {pair(c0), pair(c1)} for k+2,k+3
        ulonglong2 wd = w23[1];   // {pair(c2), pair(c3)} for k+2,k+3

        #pragma unroll
        for (int r = 0; r < 4; r++) {
            ulonglong2 xv = __ldg((const ulonglong2*)(xp + (size_t)r * ISZ + k));
            acc2[r][0] = ffma2(xv.x, wa.x,  acc2[r][0]);
            acc2[r][1] = ffma2(xv.x, wa.y,  acc2[r][1]);
            acc2[r][2] = ffma2(xv.x, wbv.x, acc2[r][2]);
            acc2[r][3] = ffma2(xv.x, wbv.y, acc2[r][3]);
            acc2[r][0] = ffma2(xv.y, wc.x,  acc2[r][0]);
            acc2[r][1] = ffma2(xv.y, wc.y,  acc2[r][1]);
            acc2[r][2] = ffma2(xv.y, wd.x,  acc2[r][2]);
            acc2[r][3] = ffma2(xv.y, wd.y,  acc2[r][3]);
        }
    }

    float4 bv = *(const float4*)(bias + col0);
    #pragma unroll
    for (int r = 0; r < 4; r++) {
        float2 a0 = unpack2(acc2[r][0]);
        float2 a1 = unpack2(acc2[r][1]);
        float2 a2 = unpack2(acc2[r][2]);
        float2 a3 = unpack2(acc2[r][3]);
        float4 o;
        o.x = a0.x + a0.y + bv.x;
        o.y = a1.x + a1.y + bv.y;
        o.z = a2.x + a2.y + bv.z;
        o.w = a3.x + a3.y + bv.w;
        *(float4*)(g_xproj + (size_t)(row0 + r) * N4 + col0) = o;
    }
}

// ---------------------------------------------------------------------------
// Software grid barrier -- atomic counter on ONE hot L2 line (measured
// fastest vs distributed flags and one-sided chunk counters)
// ---------------------------------------------------------------------------
__device__ __forceinline__ void gsync(unsigned target) {
    __syncthreads();
    if (threadIdx.x == 0) {
        __threadfence();
        atomicAdd(&g_bar, 1u);
        while (*(volatile unsigned*)&g_bar < target) { }
        __threadfence();
    }
    __syncthreads();
}

// ---------------------------------------------------------------------------
// Persistent LSTM recurrence -- EXACT R6 structure (measured best, 6039us).
// Block `blk` owns output cols {g*1024 + blk*8 + q}.
// Warp mapping: tx -> col, ty -> k-subrange [ty*32, ty*32+32) of each chunk,
// accumulating partials for ALL 32 batch rows (32 x f32x2 accumulators).
// ---------------------------------------------------------------------------
__global__ void __launch_bounds__(NTHR, 1)
lstm_persist(const float* __restrict__ W,
             const float* __restrict__ gamma,
             const float* __restrict__ beta,
             const float* __restrict__ init_cx,
             float* __restrict__ out) {
    extern __shared__ float smem[];
    float4* __restrict__ Wsf4 = (float4*)smem;               // [8192] float4
    float*  __restrict__ Hreg = smem + 32768;                // 64KB region
    float4* __restrict__ Hbuf = (float4*)Hreg;               // [2][2048] float4
    float*  __restrict__ Pred = Hreg;                        // overlay: [32][8][32]
    __shared__ float c_sm[BB * 8];

    const int tid = threadIdx.x;
    const int tx  = tid & 31, ty = tid >> 5;
    const int blk = blockIdx.x;
    const int g   = tx >> 3, q = tx & 7;
    const int gcol = g * OSZ + blk * 8 + q;
    const int b0  = ty * 4;

    // Preload W_h slice into float4 layout: smem[(k>>2)*128 + c*4 + (k&3)]
    for (int idx = tid; idx < ISZ * 32; idx += NTHR) {
        int k = idx >> 5, c = idx & 31;
        int col = (c >> 3) * OSZ + blk * 8 + (c & 7);
        smem[(k >> 2) * 128 + c * 4 + (k & 3)] = W[(size_t)(ISZ + k) * N4 + col];
    }
    if (tid < BB * 8)
        c_sm[tid] = init_cx[blk * 8 + (tid & 7)];

    const float gam = gamma[gcol];
    const float bet = beta[gcol];

    // Cooperative-load source indices (8 float4 per chunk per thread)
    int ld_r[8], ld_j[8];
    #pragma unroll
    for (int u = 0; u < 8; u++) {
        int i = u * NTHR + tid;
        ld_r[u] = i >> 6;
        ld_j[u] = i & 63;
    }
    __syncthreads();

    unsigned nsync = 0;

    // Prefetch xproj for t=0
    float px[4];
    #pragma unroll
    for (int r = 0; r < 4; r++)
        px[r] = __ldcg(&g_xproj[((size_t)(b0 + r) * SS + 0) * N4 + gcol]);

    for (int t = 0; t < SS; t++) {
        float cur[4];
        #pragma unroll
        for (int r = 0; r < 4; r++) cur[r] = px[r];
        if (t + 1 < SS) {
            #pragma unroll
            for (int r = 0; r < 4; r++)
                px[r] = __ldcg(&g_xproj[((size_t)(b0 + r) * SS + t + 1) * N4 + gcol]);
        }

        // ---- stage chunk 0 of h ----
        {
            float4 ld[8];
            #pragma unroll
            for (int u = 0; u < 8; u++)
                ld[u] = __ldcg((const float4*)(g_h + (size_t)ld_r[u] * OSZ + ld_j[u] * 4));
            #pragma unroll
            for (int u = 0; u < 8; u++)
                Hbuf[u * NTHR + tid] = ld[u];
        }
        __syncthreads();

        // ---- recurrent GEMM: warp ty covers k in [c*256+ty*32, +32) for
        //      all 32 rows; f32x2 accumulators, one per row ----
        ull acc2[32];
        #pragma unroll
        for (int r = 0; r < 32; r++) acc2[r] = 0ull;

        #pragma unroll 1
        for (int c = 0; c < NCH; c++) {
            float4 ldn[8];
            if (c < NCH - 1) {
                const int k0n = (c + 1) * CHUNK;
                #pragma unroll
                for (int u = 0; u < 8; u++)
                    ldn[u] = __ldcg((const float4*)(g_h + (size_t)ld_r[u] * OSZ + k0n + ld_j[u] * 4));
            }

            const float4* __restrict__ hb = Hbuf + (c & 1) * 2048;
            const ulonglong2* __restrict__ wp =
                (const ulonglong2*)Wsf4 + (size_t)(c * 64 + ty * 8) * 32 + tx;

            #pragma unroll 4
            for (int jj = 0; jj < 8; jj++) {
                ulonglong2 wv = wp[jj * 32];            // {w[k],w[k+1]},{w[k+2],w[k+3]}
                const ulonglong2* __restrict__ hj =
                    (const ulonglong2*)(hb + (ty * 8 + jj));
                #pragma unroll
                for (int r = 0; r < 32; r++) {
                    ulonglong2 hv = hj[r * 64];         // broadcast: h[r][k..k+3]
                    acc2[r] = ffma2(hv.x, wv.x, acc2[r]);
                    acc2[r] = ffma2(hv.y, wv.y, acc2[r]);
                }
            }

            if (c < NCH - 1) {
                float4* __restrict__ hn = Hbuf + ((c + 1) & 1) * 2048;
                #pragma unroll
                for (int u = 0; u < 8; u++)
                    hn[u * NTHR + tid] = ldn[u];
                __syncthreads();
            }
        }

        // ---- cross-warp k-reduction via SMEM overlay ----
        #pragma unroll
        for (int r = 0; r < 32; r++) {
            float2 a = unpack2(acc2[r]);
            Pred[(r * 8 + ty) * 32 + tx] = a.x + a.y;
        }
        __syncthreads();

        float acc[4];
        #pragma unroll
        for (int r = 0; r < 4; r++) {
            const int row = b0 + r;
            float sum = 0.f;
            #pragma unroll
            for (int w = 0; w < 8; w++)
                sum += Pred[(row * 8 + w) * 32 + tx];
            acc[r] = sum + cur[r];
        }

        // ---- LN partial sums over this block's 32 columns, per row ----
        float s[4], ss[4];
        #pragma unroll
        for (int r = 0; r < 4; r++) { s[r] = acc[r]; ss[r] = acc[r] * acc[r]; }
        #pragma unroll
        for (int o = 16; o > 0; o >>= 1) {
            #pragma unroll
            for (int r = 0; r < 4; r++) {
                s[r]  += __shfl_xor_sync(0xffffffffu, s[r],  o);
                ss[r] += __shfl_xor_sync(0xffffffffu, ss[r], o);
            }
        }
        if (tx == 0) {
            #pragma unroll
            for (int r = 0; r < 4; r++) {
                __stcg(&g_part[0][b0 + r][blk], s[r]);
                __stcg(&g_part[1][b0 + r][blk], ss[r]);
            }
        }

        gsync(++nsync * NBLK);

        // ---- aggregate stats (deterministic): warp ty handles rows b0..b0+3 ----
        float mean[4], rstd[4];
        #pragma unroll
        for (int r = 0; r < 4; r++) {
            int row = b0 + r;
            float4 sv = __ldcg((const float4*)&g_part[0][row][tx * 4]);
            float4 qv = __ldcg((const float4*)&g_part[1][row][tx * 4]);
            float sl = (sv.x + sv.y) + (sv.z + sv.w);
            float ql = (qv.x + qv.y) + (qv.z + qv.w);
            #pragma unroll
            for (int o = 16; o > 0; o >>= 1) {
                sl += __shfl_xor_sync(0xffffffffu, sl, o);
                ql += __shfl_xor_sync(0xffffffffu, ql, o);
            }
            float m = sl * (1.0f / N4);
            mean[r] = m;
            rstd[r] = rsqrtf(ql * (1.0f / N4) - m * m + EPSF);
        }

        // ---- LN + gates. Gates of index i sit in lanes q, q+8, q+16, q+24 ----
        #pragma unroll
        for (int r = 0; r < 4; r++) {
            float v = (acc[r] - mean[r]) * rstd[r] * gam + bet;
            float a0 = __shfl_sync(0xffffffffu, v, q);        // ig
            float a1 = __shfl_sync(0xffffffffu, v, q + 8);    // fg
            float a2 = __shfl_sync(0xffffffffu, v, q + 16);   // hidden
            float a3 = __shfl_sync(0xffffffffu, v, q + 24);   // og
            if (g == 0) {
                int b = b0 + r;
                int i = blk * 8 + q;
                float si = 1.0f / (1.0f + expf(-a0));
                float sf = 1.0f / (1.0f + expf(-a1));
                float so = 1.0f / (1.0f + expf(-a3));
                float co = c_sm[b * 8 + q];
                float cn = sf * co + si * tanhf(a2);
                float h  = so * cn;
                c_sm[b * 8 + q] = cn;
                __stcg(&g_h[(size_t)b * OSZ + i], h);
                out[((size_t)b * SS + t) * OSZ + i] = h;
            }
        }

        gsync(++nsync * NBLK);
    }
}

// ---------------------------------------------------------------------------
// Inputs (metadata order): x, W, b, gamma, beta, init_hx, init_cx
// ---------------------------------------------------------------------------
extern "C" void kernel_launch(void* const* d_in, const int* in_sizes, int n_in,
                              void* d_out, int out_size) {
    const float* x       = (const float*)d_in[0];
    const float* W       = (const float*)d_in[1];
    const float* bias    = (const float*)d_in[2];
    const float* gamma   = (const float*)d_in[3];
    const float* beta    = (const float*)d_in[4];
    const float* init_hx = (const float*)d_in[5];
    const float* init_cx = (const float*)d_in[6];
    float* out = (float*)d_out;

    // 128 blocks: must cover BB*OSZ = 32768 h elements
    init_state<<<(BB * OSZ + 255) / 256, 256>>>(init_hx);

    // Prepack W_x into k-pair-interleaved layout (512*4096 pairs)
    prepack_w<<<(512 * N4) / 256, 256>>>(W);

    dim3 blk(32, 8);
    xproj_kernel<<<dim3(32, 256), blk>>>(x, bias);

    cudaFuncSetAttribute(lstm_persist,
                         cudaFuncAttributeMaxDynamicSharedMemorySize, 196608);
    lstm_persist<<<NBLK, NTHR, 196608>>>(W, gamma, beta, init_cx, out);
}

// round 14
// speedup vs baseline: 1.2341x; 1.1310x over previous
#include <cuda_runtime.h>
#include <cuda_bf16.h>
#include <math.h>
#include <stdint.h>

#define BB     32
#define SS     256
#define ISZ    1024
#define OSZ    1024
#define N4     4096
#define EPSF   1e-5f
#define NBLK   128
#define NTHR   256
#define CHUNK  256                 // k-extent per staged chunk (persist)
#define NCH    4                   // 1024 / 256

typedef unsigned long long ull;

// Scratch (device globals -- no runtime allocation allowed)
__device__ float         g_xproj[BB * SS * N4];   // x @ W_x + b for all timesteps
__device__ __nv_bfloat16 g_xh[BB * SS * ISZ];     // bf16 hi split of x
__device__ __nv_bfloat16 g_xl[BB * SS * ISZ];     // bf16 lo split of x
__device__ __nv_bfloat16 g_wh[ISZ * N4];          // bf16 hi split of W_x
__device__ __nv_bfloat16 g_wl[ISZ * N4];          // bf16 lo split of W_x
__device__ float         g_h[BB * OSZ];           // hidden state
__device__ float         g_part[2][BB][NBLK];     // LN partials [stat][row][blk]
__device__ unsigned      g_bar;                   // grid barrier counter

// ---------------------------------------------------------------------------
// Packed f32x2 helpers (persist kernel -- proven 6039us config)
// ---------------------------------------------------------------------------
__device__ __forceinline__ ull ffma2(ull a, ull b, ull c) {
    ull d;
    asm("fma.rn.f32x2 %0, %1, %2, %3;" : "=l"(d) : "l"(a), "l"(b), "l"(c));
    return d;
}
__device__ __forceinline__ float2 unpack2(ull v) {
    float2 r;
    asm("mov.b64 {%0, %1}, %2;" : "=f"(r.x), "=f"(r.y) : "l"(v));
    return r;
}

// ---------------------------------------------------------------------------
// Init: h from init_hx (broadcast over batch), reset barrier.
// ---------------------------------------------------------------------------
__global__ void init_state(const float* __restrict__ init_hx) {
    int j = blockIdx.x * blockDim.x + threadIdx.x;
    if (j == 0) g_bar = 0;
    if (j < BB * OSZ) g_h[j] = init_hx[j & (OSZ - 1)];
}

// ---------------------------------------------------------------------------
// bf16 splits: v = hi + lo with |lo residual| ~ 2^-16 |v|
// ---------------------------------------------------------------------------
__global__ void split_x(const float* __restrict__ x) {
    int i = blockIdx.x * blockDim.x + threadIdx.x;   // covers BB*SS*ISZ exactly
    float v = x[i];
    __nv_bfloat16 hi = __float2bfloat16(v);
    g_xh[i] = hi;
    g_xl[i] = __float2bfloat16(v - __bfloat162float(hi));
}
__global__ void split_w(const float* __restrict__ W) {
    int i = blockIdx.x * blockDim.x + threadIdx.x;   // covers ISZ*N4 exactly
    float v = W[i];
    __nv_bfloat16 hi = __float2bfloat16(v);
    g_wh[i] = hi;
    g_wl[i] = __float2bfloat16(v - __bfloat162float(hi));
}

// ---------------------------------------------------------------------------
// Tensor-core xproj: g_xproj = x @ W_x + b via bf16x3 (xh@wh + xh@wl + xl@wh),
// fused as one K=3072 GEMM. Block tile 128M x 64N, 8 warps of 32x32,
// mma.sync.m16n8k16.bf16 with fp32 accumulators.
// SMEM word layouts (padded rows of 20 words -> conflict-free frag loads):
//   Aw[r][c]  : r in [0,128), c = k-pair in [0,16)   (A row-major)
//   Bw[n][c]  : n in [0,64),  c = k-pair in [0,16)   (B stored transposed)
// ---------------------------------------------------------------------------
__global__ void __launch_bounds__(256)
xproj_mma(const float* __restrict__ bias) {
    __shared__ uint32_t Aw[128 * 20];
    __shared__ uint32_t Bw[64 * 20];

    const int tid  = threadIdx.x;
    const int lane = tid & 31, wid = tid >> 5;
    const int wm   = wid >> 1;        // 0..3  (m warp tile)
    const int wn   = wid & 1;         // 0..1  (n warp tile)
    const int m0   = blockIdx.y * 128;
    const int n0   = blockIdx.x * 64;

    const uint32_t* xh_w = (const uint32_t*)g_xh;
    const uint32_t* xl_w = (const uint32_t*)g_xl;
    const uint32_t* wh_w = (const uint32_t*)g_wh;
    const uint32_t* wl_w = (const uint32_t*)g_wl;

    float d[2][4][4];
    #pragma unroll
    for (int mt = 0; mt < 2; mt++)
        #pragma unroll
        for (int nt = 0; nt < 4; nt++)
            #pragma unroll
            for (int e = 0; e < 4; e++) d[mt][nt][e] = 0.f;

    const int gr = lane >> 2;         // fragment row/col group 0..7
    const int gc = lane & 3;          // fragment k-pair group 0..3

    for (int cc = 0; cc < 96; cc++) {          // 3 segments x 32 chunks of k=32
        const int seg = cc >> 5, kc = cc & 31;
        const uint32_t* As = (seg < 2) ? xh_w : xl_w;
        const uint32_t* Bs = (seg == 1) ? wl_w : wh_w;

        if (cc) __syncthreads();               // compute done before overwrite

        // stage A: 128 rows x 16 k-pair words
        #pragma unroll
        for (int u = 0; u < 8; u++) {
            int idx = u * 256 + tid;
            int r = idx >> 4, c = idx & 15;
            Aw[r * 20 + c] = As[(size_t)(m0 + r) * 512 + kc * 16 + c];
        }
        // stage B transposed: Bw[n][k] = Wseg[kk0+k][n0+n]
        #pragma unroll
        for (int u = 0; u < 4; u++) {
            int idx = u * 256 + tid;
            int k = idx >> 5, nw = idx & 31;
            uint32_t v = Bs[(size_t)(kc * 32 + k) * 2048 + (n0 >> 1) + nw];
            uint16_t* bh = (uint16_t*)Bw;
            bh[(2 * nw)     * 40 + k] = (uint16_t)(v & 0xffffu);
            bh[(2 * nw + 1) * 40 + k] = (uint16_t)(v >> 16);
        }
        __syncthreads();

        #pragma unroll
        for (int ks = 0; ks < 2; ks++) {       // two k16 halves of the chunk
            uint32_t a[2][4];
            #pragma unroll
            for (int mt = 0; mt < 2; mt++) {
                int rb = wm * 32 + mt * 16;
                a[mt][0] = Aw[(rb + gr)     * 20 + ks * 8 + gc];
                a[mt][1] = Aw[(rb + 8 + gr) * 20 + ks * 8 + gc];
                a[mt][2] = Aw[(rb + gr)     * 20 + ks * 8 + 4 + gc];
                a[mt][3] = Aw[(rb + 8 + gr) * 20 + ks * 8 + 4 + gc];
            }
            #pragma unroll
            for (int nt = 0; nt < 4; nt++) {
                int nb = wn * 32 + nt * 8;
                uint32_t b0 = Bw[(nb + gr) * 20 + ks * 8 + gc];
                uint32_t b1 = Bw[(nb + gr) * 20 + ks * 8 + 4 + gc];
                #pragma unroll
                for (int mt = 0; mt < 2; mt++) {
                    asm("mma.sync.aligned.m16n8k16.row.col.f32.bf16.bf16.f32 "
                        "{%0,%1,%2,%3}, {%4,%5,%6,%7}, {%8,%9}, {%0,%1,%2,%3};"
                        : "+f"(d[mt][nt][0]), "+f"(d[mt][nt][1]),
                          "+f"(d[mt][nt][2]), "+f"(d[mt][nt][3])
                        : "r"(a[mt][0]), "r"(a[mt][1]), "r"(a[mt][2]), "r"(a[mt][3]),
                          "r"(b0), "r"(b1));
                }
            }
        }
    }

    // epilogue: + bias, fp32 stores
    #pragma unroll
    for (int mt = 0; mt < 2; mt++) {
        #pragma unroll
        for (int nt = 0; nt < 4; nt++) {
            int row = m0 + wm * 32 + mt * 16 + gr;
            int col = n0 + wn * 32 + nt * 8 + gc * 2;
            float2 bv = *(const float2*)(bias + col);
            float2 v0 = { d[mt][nt][0] + bv.x, d[mt][nt][1] + bv.y };
            float2 v1 = { d[mt][nt][2] + bv.x, d[mt][nt][3] + bv.y };
            *(float2*)(g_xproj + (size_t)row * N4 + col)       = v0;
            *(float2*)(g_xproj + (size_t)(row + 8) * N4 + col) = v1;
        }
    }
}

// ---------------------------------------------------------------------------
// Software grid barrier -- atomic counter on ONE hot L2 line (measured best)
// ---------------------------------------------------------------------------
__device__ __forceinline__ void gsync(unsigned target) {
    __syncthreads();
    if (threadIdx.x == 0) {
        __threadfence();
        atomicAdd(&g_bar, 1u);
        while (*(volatile unsigned*)&g_bar < target) { }
        __threadfence();
    }
    __syncthreads();
}

// ---------------------------------------------------------------------------
// Persistent LSTM recurrence -- EXACT 6039us structure (unchanged).
// ---------------------------------------------------------------------------
__global__ void __launch_bounds__(NTHR, 1)
lstm_persist(const float* __restrict__ W,
             const float* __restrict__ gamma,
             const float* __restrict__ beta,
             const float* __restrict__ init_cx,
             float* __restrict__ out) {
    extern __shared__ float smem[];
    float4* __restrict__ Wsf4 = (float4*)smem;               // [8192] float4
    float*  __restrict__ Hreg = smem + 32768;                // 64KB region
    float4* __restrict__ Hbuf = (float4*)Hreg;               // [2][2048] float4
    float*  __restrict__ Pred = Hreg;                        // overlay: [32][8][32]
    __shared__ float c_sm[BB * 8];

    const int tid = threadIdx.x;
    const int tx  = tid & 31, ty = tid >> 5;
    const int blk = blockIdx.x;
    const int g   = tx >> 3, q = tx & 7;
    const int gcol = g * OSZ + blk * 8 + q;
    const int b0  = ty * 4;

    for (int idx = tid; idx < ISZ * 32; idx += NTHR) {
        int k = idx >> 5, c = idx & 31;
        int col = (c >> 3) * OSZ + blk * 8 + (c & 7);
        smem[(k >> 2) * 128 + c * 4 + (k & 3)] = W[(size_t)(ISZ + k) * N4 + col];
    }
    if (tid < BB * 8)
        c_sm[tid] = init_cx[blk * 8 + (tid & 7)];

    const float gam = gamma[gcol];
    const float bet = beta[gcol];

    int ld_r[8], ld_j[8];
    #pragma unroll
    for (int u = 0; u < 8; u++) {
        int i = u * NTHR + tid;
        ld_r[u] = i >> 6;
        ld_j[u] = i & 63;
    }
    __syncthreads();

    unsigned nsync = 0;

    float px[4];
    #pragma unroll
    for (int r = 0; r < 4; r++)
        px[r] = __ldcg(&g_xproj[((size_t)(b0 + r) * SS + 0) * N4 + gcol]);

    for (int t = 0; t < SS; t++) {
        float cur[4];
        #pragma unroll
        for (int r = 0; r < 4; r++) cur[r] = px[r];
        if (t + 1 < SS) {
            #pragma unroll
            for (int r = 0; r < 4; r++)
                px[r] = __ldcg(&g_xproj[((size_t)(b0 + r) * SS + t + 1) * N4 + gcol]);
        }

        {
            float4 ld[8];
            #pragma unroll
            for (int u = 0; u < 8; u++)
                ld[u] = __ldcg((const float4*)(g_h + (size_t)ld_r[u] * OSZ + ld_j[u] * 4));
            #pragma unroll
            for (int u = 0; u < 8; u++)
                Hbuf[u * NTHR + tid] = ld[u];
        }
        __syncthreads();

        ull acc2[32];
        #pragma unroll
        for (int r = 0; r < 32; r++) acc2[r] = 0ull;

        #pragma unroll 1
        for (int c = 0; c < NCH; c++) {
            float4 ldn[8];
            if (c < NCH - 1) {
                const int k0n = (c + 1) * CHUNK;
                #pragma unroll
                for (int u = 0; u < 8; u++)
                    ldn[u] = __ldcg((const float4*)(g_h + (size_t)ld_r[u] * OSZ + k0n + ld_j[u] * 4));
            }

            const float4* __restrict__ hb = Hbuf + (c & 1) * 2048;
            const ulonglong2* __restrict__ wp =
                (const ulonglong2*)Wsf4 + (size_t)(c * 64 + ty * 8) * 32 + tx;

            #pragma unroll 4
            for (int jj = 0; jj < 8; jj++) {
                ulonglong2 wv = wp[jj * 32];
                const ulonglong2* __restrict__ hj =
                    (const ulonglong2*)(hb + (ty * 8 + jj));
                #pragma unroll
                for (int r = 0; r < 32; r++) {
                    ulonglong2 hv = hj[r * 64];
                    acc2[r] = ffma2(hv.x, wv.x, acc2[r]);
                    acc2[r] = ffma2(hv.y, wv.y, acc2[r]);
                }
            }

            if (c < NCH - 1) {
                float4* __restrict__ hn = Hbuf + ((c + 1) & 1) * 2048;
                #pragma unroll
                for (int u = 0; u < 8; u++)
                    hn[u * NTHR + tid] = ldn[u];
                __syncthreads();
            }
        }

        #pragma unroll
        for (int r = 0; r < 32; r++) {
            float2 a = unpack2(acc2[r]);
            Pred[(r * 8 + ty) * 32 + tx] = a.x + a.y;
        }
        __syncthreads();

        float acc[4];
        #pragma unroll
        for (int r = 0; r < 4; r++) {
            const int row = b0 + r;
            float sum = 0.f;
            #pragma unroll
            for (int w = 0; w < 8; w++)
                sum += Pred[(row * 8 + w) * 32 + tx];
            acc[r] = sum + cur[r];
        }

        float s[4], ss[4];
        #pragma unroll
        for (int r = 0; r < 4; r++) { s[r] = acc[r]; ss[r] = acc[r] * acc[r]; }
        #pragma unroll
        for (int o = 16; o > 0; o >>= 1) {
            #pragma unroll
            for (int r = 0; r < 4; r++) {
                s[r]  += __shfl_xor_sync(0xffffffffu, s[r],  o);
                ss[r] += __shfl_xor_sync(0xffffffffu, ss[r], o);
            }
        }
        if (tx == 0) {
            #pragma unroll
            for (int r = 0; r < 4; r++) {
                __stcg(&g_part[0][b0 + r][blk], s[r]);
                __stcg(&g_part[1][b0 + r][blk], ss[r]);
            }
        }

        gsync(++nsync * NBLK);

        float mean[4], rstd[4];
        #pragma unroll
        for (int r = 0; r < 4; r++) {
            int row = b0 + r;
            float4 sv = __ldcg((const float4*)&g_part[0][row][tx * 4]);
            float4 qv = __ldcg((const float4*)&g_part[1][row][tx * 4]);
            float sl = (sv.x + sv.y) + (sv.z + sv.w);
            float ql = (qv.x + qv.y) + (qv.z + qv.w);
            #pragma unroll
            for (int o = 16; o > 0; o >>= 1) {
                sl += __shfl_xor_sync(0xffffffffu, sl, o);
                ql += __shfl_xor_sync(0xffffffffu, ql, o);
            }
            float m = sl * (1.0f / N4);
            mean[r] = m;
            rstd[r] = rsqrtf(ql * (1.0f / N4) - m * m + EPSF);
        }

        #pragma unroll
        for (int r = 0; r < 4; r++) {
            float v = (acc[r] - mean[r]) * rstd[r] * gam + bet;
            float a0 = __shfl_sync(0xffffffffu, v, q);
            float a1 = __shfl_sync(0xffffffffu, v, q + 8);
            float a2 = __shfl_sync(0xffffffffu, v, q + 16);
            float a3 = __shfl_sync(0xffffffffu, v, q + 24);
            if (g == 0) {
                int b = b0 + r;
                int i = blk * 8 + q;
                float si = 1.0f / (1.0f + expf(-a0));
                float sf = 1.0f / (1.0f + expf(-a1));
                float so = 1.0f / (1.0f + expf(-a3));
                float co = c_sm[b * 8 + q];
                float cn = sf * co + si * tanhf(a2);
                float h  = so * cn;
                c_sm[b * 8 + q] = cn;
                __stcg(&g_h[(size_t)b * OSZ + i], h);
                out[((size_t)b * SS + t) * OSZ + i] = h;
            }
        }

        gsync(++nsync * NBLK);
    }
}

// ---------------------------------------------------------------------------
// Inputs (metadata order): x, W, b, gamma, beta, init_hx, init_cx
// ---------------------------------------------------------------------------
extern "C" void kernel_launch(void* const* d_in, const int* in_sizes, int n_in,
                              void* d_out, int out_size) {
    const float* x       = (const float*)d_in[0];
    const float* W       = (const float*)d_in[1];
    const float* bias    = (const float*)d_in[2];
    const float* gamma   = (const float*)d_in[3];
    const float* beta    = (const float*)d_in[4];
    const float* init_hx = (const float*)d_in[5];
    const float* init_cx = (const float*)d_in[6];
    float* out = (float*)d_out;

    init_state<<<(BB * OSZ + 255) / 256, 256>>>(init_hx);

    split_x<<<(BB * SS * ISZ) / 256, 256>>>(x);
    split_w<<<(ISZ * N4) / 256, 256>>>(W);

    xproj_mma<<<dim3(N4 / 64, (BB * SS) / 128), 256>>>(bias);

    cudaFuncSetAttribute(lstm_persist,
                         cudaFuncAttributeMaxDynamicSharedMemorySize, 196608);
    lstm_persist<<<NBLK, NTHR, 196608>>>(W, gamma, beta, init_cx, out);
}

// round 15
// speedup vs baseline: 1.2575x; 1.0190x over previous
#include <cuda_runtime.h>
#include <cuda_bf16.h>
#include <math.h>
#include <stdint.h>

#define BB     32
#define SS     256
#define ISZ    1024
#define OSZ    1024
#define N4     4096
#define EPSF   1e-5f
#define NBLK   128
#define NTHR   512
#define CHUNK  256                 // k-extent per staged chunk (persist)
#define NCH    4                   // 1024 / 256

typedef unsigned long long ull;

// Scratch (device globals -- no runtime allocation allowed)
__device__ float         g_xproj[BB * SS * N4];   // x @ W_x + b for all timesteps
__device__ __nv_bfloat16 g_xh[BB * SS * ISZ];     // bf16 hi split of x
__device__ __nv_bfloat16 g_xl[BB * SS * ISZ];     // bf16 lo split of x
__device__ __nv_bfloat16 g_wh[ISZ * N4];          // bf16 hi split of W_x
__device__ __nv_bfloat16 g_wl[ISZ * N4];          // bf16 lo split of W_x
__device__ float         g_h[BB * OSZ];           // hidden state
__device__ float         g_part[2][BB][NBLK];     // LN partials [stat][row][blk]
__device__ unsigned      g_bar;                   // grid barrier counter

// ---------------------------------------------------------------------------
// Packed f32x2 helpers
// ---------------------------------------------------------------------------
__device__ __forceinline__ ull ffma2(ull a, ull b, ull c) {
    ull d;
    asm("fma.rn.f32x2 %0, %1, %2, %3;" : "=l"(d) : "l"(a), "l"(b), "l"(c));
    return d;
}
__device__ __forceinline__ float2 unpack2(ull v) {
    float2 r;
    asm("mov.b64 {%0, %1}, %2;" : "=f"(r.x), "=f"(r.y) : "l"(v));
    return r;
}

// ---------------------------------------------------------------------------
// Init: h from init_hx (broadcast over batch), reset barrier.
// ---------------------------------------------------------------------------
__global__ void init_state(const float* __restrict__ init_hx) {
    int j = blockIdx.x * blockDim.x + threadIdx.x;
    if (j == 0) g_bar = 0;
    if (j < BB * OSZ) g_h[j] = init_hx[j & (OSZ - 1)];
}

// ---------------------------------------------------------------------------
// bf16 splits: v = hi + lo with |lo residual| ~ 2^-16 |v|
// ---------------------------------------------------------------------------
__global__ void split_x(const float* __restrict__ x) {
    int i = blockIdx.x * blockDim.x + threadIdx.x;
    float v = x[i];
    __nv_bfloat16 hi = __float2bfloat16(v);
    g_xh[i] = hi;
    g_xl[i] = __float2bfloat16(v - __bfloat162float(hi));
}
__global__ void split_w(const float* __restrict__ W) {
    int i = blockIdx.x * blockDim.x + threadIdx.x;
    float v = W[i];
    __nv_bfloat16 hi = __float2bfloat16(v);
    g_wh[i] = hi;
    g_wl[i] = __float2bfloat16(v - __bfloat162float(hi));
}

// ---------------------------------------------------------------------------
// Tensor-core xproj (proven R14): bf16x3 fused K=3072 GEMM, 128x64 tiles.
// ---------------------------------------------------------------------------
__global__ void __launch_bounds__(256)
xproj_mma(const float* __restrict__ bias) {
    __shared__ uint32_t Aw[128 * 20];
    __shared__ uint32_t Bw[64 * 20];

    const int tid  = threadIdx.x;
    const int lane = tid & 31, wid = tid >> 5;
    const int wm   = wid >> 1;
    const int wn   = wid & 1;
    const int m0   = blockIdx.y * 128;
    const int n0   = blockIdx.x * 64;

    const uint32_t* xh_w = (const uint32_t*)g_xh;
    const uint32_t* xl_w = (const uint32_t*)g_xl;
    const uint32_t* wh_w = (const uint32_t*)g_wh;
    const uint32_t* wl_w = (const uint32_t*)g_wl;

    float d[2][4][4];
    #pragma unroll
    for (int mt = 0; mt < 2; mt++)
        #pragma unroll
        for (int nt = 0; nt < 4; nt++)
            #pragma unroll
            for (int e = 0; e < 4; e++) d[mt][nt][e] = 0.f;

    const int gr = lane >> 2;
    const int gc = lane & 3;

    for (int cc = 0; cc < 96; cc++) {
        const int seg = cc >> 5, kc = cc & 31;
        const uint32_t* As = (seg < 2) ? xh_w : xl_w;
        const uint32_t* Bs = (seg == 1) ? wl_w : wh_w;

        if (cc) __syncthreads();

        #pragma unroll
        for (int u = 0; u < 8; u++) {
            int idx = u * 256 + tid;
            int r = idx >> 4, c = idx & 15;
            Aw[r * 20 + c] = As[(size_t)(m0 + r) * 512 + kc * 16 + c];
        }
        #pragma unroll
        for (int u = 0; u < 4; u++) {
            int idx = u * 256 + tid;
            int k = idx >> 5, nw = idx & 31;
            uint32_t v = Bs[(size_t)(kc * 32 + k) * 2048 + (n0 >> 1) + nw];
            uint16_t* bh = (uint16_t*)Bw;
            bh[(2 * nw)     * 40 + k] = (uint16_t)(v & 0xffffu);
            bh[(2 * nw + 1) * 40 + k] = (uint16_t)(v >> 16);
        }
        __syncthreads();

        #pragma unroll
        for (int ks = 0; ks < 2; ks++) {
            uint32_t a[2][4];
            #pragma unroll
            for (int mt = 0; mt < 2; mt++) {
                int rb = wm * 32 + mt * 16;
                a[mt][0] = Aw[(rb + gr)     * 20 + ks * 8 + gc];
                a[mt][1] = Aw[(rb + 8 + gr) * 20 + ks * 8 + gc];
                a[mt][2] = Aw[(rb + gr)     * 20 + ks * 8 + 4 + gc];
                a[mt][3] = Aw[(rb + 8 + gr) * 20 + ks * 8 + 4 + gc];
            }
            #pragma unroll
            for (int nt = 0; nt < 4; nt++) {
                int nb = wn * 32 + nt * 8;
                uint32_t b0 = Bw[(nb + gr) * 20 + ks * 8 + gc];
                uint32_t b1 = Bw[(nb + gr) * 20 + ks * 8 + 4 + gc];
                #pragma unroll
                for (int mt = 0; mt < 2; mt++) {
                    asm("mma.sync.aligned.m16n8k16.row.col.f32.bf16.bf16.f32 "
                        "{%0,%1,%2,%3}, {%4,%5,%6,%7}, {%8,%9}, {%0,%1,%2,%3};"
                        : "+f"(d[mt][nt][0]), "+f"(d[mt][nt][1]),
                          "+f"(d[mt][nt][2]), "+f"(d[mt][nt][3])
                        : "r"(a[mt][0]), "r"(a[mt][1]), "r"(a[mt][2]), "r"(a[mt][3]),
                          "r"(b0), "r"(b1));
                }
            }
        }
    }

    #pragma unroll
    for (int mt = 0; mt < 2; mt++) {
        #pragma unroll
        for (int nt = 0; nt < 4; nt++) {
            int row = m0 + wm * 32 + mt * 16 + gr;
            int col = n0 + wn * 32 + nt * 8 + gc * 2;
            float2 bv = *(const float2*)(bias + col);
            float2 v0 = { d[mt][nt][0] + bv.x, d[mt][nt][1] + bv.y };
            float2 v1 = { d[mt][nt][2] + bv.x, d[mt][nt][3] + bv.y };
            *(float2*)(g_xproj + (size_t)row * N4 + col)       = v0;
            *(float2*)(g_xproj + (size_t)(row + 8) * N4 + col) = v1;
        }
    }
}

// ---------------------------------------------------------------------------
// Software grid barrier -- atomic counter on ONE hot L2 line (measured best)
// ---------------------------------------------------------------------------
__device__ __forceinline__ void gsync(unsigned target) {
    __syncthreads();
    if (threadIdx.x == 0) {
        __threadfence();
        atomicAdd(&g_bar, 1u);
        while (*(volatile unsigned*)&g_bar < target) { }
        __threadfence();
    }
    __syncthreads();
}

// ---------------------------------------------------------------------------
// Persistent LSTM recurrence -- R6 dataflow at 512 threads (16 warps).
// Warp (ky = ty&7, rh = ty>>3): k-part ky (8-way, SAME as R6 -> reduction
// size unchanged) x row-half rh (rows rh*16..rh*16+15, 16 accumulators).
// Doubles warps/SMSP 2->4 to fill latency bubbles (R13 ncu: all pipes <55%).
// LN/stats/gates identical to R6 on warps 0-7.
// ---------------------------------------------------------------------------
__global__ void __launch_bounds__(NTHR, 1)
lstm_persist(const float* __restrict__ W,
             const float* __restrict__ gamma,
             const float* __restrict__ beta,
             const float* __restrict__ init_cx,
             float* __restrict__ out) {
    extern __shared__ float smem[];
    float4* __restrict__ Wsf4 = (float4*)smem;               // [8192] float4
    float*  __restrict__ Hreg = smem + 32768;                // 64KB region
    float4* __restrict__ Hbuf = (float4*)Hreg;               // [2][2048] float4
    float*  __restrict__ Pred = Hreg;                        // overlay: [32][8][32]
    __shared__ float c_sm[BB * 8];

    const int tid = threadIdx.x;
    const int tx  = tid & 31, ty = tid >> 5;
    const int ky  = ty & 7;            // k-part (8-way)
    const int rh  = ty >> 3;           // row-half (0/1)
    const int rbase = rh * 16;
    const int blk = blockIdx.x;
    const int g   = tx >> 3, q = tx & 7;
    const int gcol = g * OSZ + blk * 8 + q;
    const int b0  = (ty & 7) * 4;      // consumer rows (valid for ty < 8)

    // Preload W_h slice into float4 layout: smem[(k>>2)*128 + c*4 + (k&3)]
    for (int idx = tid; idx < ISZ * 32; idx += NTHR) {
        int k = idx >> 5, c = idx & 31;
        int col = (c >> 3) * OSZ + blk * 8 + (c & 7);
        smem[(k >> 2) * 128 + c * 4 + (k & 3)] = W[(size_t)(ISZ + k) * N4 + col];
    }
    if (tid < BB * 8)
        c_sm[tid] = init_cx[blk * 8 + (tid & 7)];

    const float gam = gamma[gcol];
    const float bet = beta[gcol];

    // Cooperative-load source indices (4 float4 per chunk per thread)
    int ld_r[4], ld_j[4];
    #pragma unroll
    for (int u = 0; u < 4; u++) {
        int i = u * NTHR + tid;
        ld_r[u] = i >> 6;
        ld_j[u] = i & 63;
    }
    __syncthreads();

    unsigned nsync = 0;

    // Prefetch xproj for t=0 (consumer warps only)
    float px[4] = {0.f, 0.f, 0.f, 0.f};
    if (ty < 8) {
        #pragma unroll
        for (int r = 0; r < 4; r++)
            px[r] = __ldcg(&g_xproj[((size_t)(b0 + r) * SS + 0) * N4 + gcol]);
    }

    for (int t = 0; t < SS; t++) {
        float cur[4];
        #pragma unroll
        for (int r = 0; r < 4; r++) cur[r] = px[r];
        if (ty < 8 && t + 1 < SS) {
            #pragma unroll
            for (int r = 0; r < 4; r++)
                px[r] = __ldcg(&g_xproj[((size_t)(b0 + r) * SS + t + 1) * N4 + gcol]);
        }

        // ---- stage chunk 0 of h ----
        {
            float4 ld[4];
            #pragma unroll
            for (int u = 0; u < 4; u++)
                ld[u] = __ldcg((const float4*)(g_h + (size_t)ld_r[u] * OSZ + ld_j[u] * 4));
            #pragma unroll
            for (int u = 0; u < 4; u++)
                Hbuf[u * NTHR + tid] = ld[u];
        }
        __syncthreads();

        // ---- recurrent GEMM: warp (ky, rh) covers k in [c*256+ky*32, +32)
        //      for rows rbase..rbase+15; 16 f32x2 accumulators ----
        ull acc2[16];
        #pragma unroll
        for (int r = 0; r < 16; r++) acc2[r] = 0ull;

        #pragma unroll 1
        for (int c = 0; c < NCH; c++) {
            float4 ldn[4];
            if (c < NCH - 1) {
                const int k0n = (c + 1) * CHUNK;
                #pragma unroll
                for (int u = 0; u < 4; u++)
                    ldn[u] = __ldcg((const float4*)(g_h + (size_t)ld_r[u] * OSZ + k0n + ld_j[u] * 4));
            }

            const float4* __restrict__ hb = Hbuf + (c & 1) * 2048;
            const ulonglong2* __restrict__ wp =
                (const ulonglong2*)Wsf4 + (size_t)(c * 64 + ky * 8) * 32 + tx;

            #pragma unroll 4
            for (int jj = 0; jj < 8; jj++) {
                ulonglong2 wv = wp[jj * 32];            // {w[k],w[k+1]},{w[k+2],w[k+3]}
                const ulonglong2* __restrict__ hj =
                    (const ulonglong2*)(hb + (ky * 8 + jj));
                #pragma unroll
                for (int r = 0; r < 16; r++) {
                    ulonglong2 hv = hj[(rbase + r) * 64];   // broadcast
                    acc2[r] = ffma2(hv.x, wv.x, acc2[r]);
                    acc2[r] = ffma2(hv.y, wv.y, acc2[r]);
                }
            }

            if (c < NCH - 1) {
                float4* __restrict__ hn = Hbuf + ((c + 1) & 1) * 2048;
                #pragma unroll
                for (int u = 0; u < 4; u++)
                    hn[u * NTHR + tid] = ldn[u];
                __syncthreads();
            }
        }

        // ---- cross-warp k-reduction via SMEM overlay [32][8][32] ----
        #pragma unroll
        for (int r = 0; r < 16; r++) {
            float2 a = unpack2(acc2[r]);
            Pred[((rbase + r) * 8 + ky) * 32 + tx] = a.x + a.y;
        }
        __syncthreads();

        float acc[4] = {0.f, 0.f, 0.f, 0.f};
        if (ty < 8) {
            #pragma unroll
            for (int r = 0; r < 4; r++) {
                const int row = b0 + r;
                float sum = 0.f;
                #pragma unroll
                for (int w = 0; w < 8; w++)
                    sum += Pred[(row * 8 + w) * 32 + tx];
                acc[r] = sum + cur[r];
            }

            // ---- LN partial sums over this block's 32 columns, per row ----
            float s[4], ss[4];
            #pragma unroll
            for (int r = 0; r < 4; r++) { s[r] = acc[r]; ss[r] = acc[r] * acc[r]; }
            #pragma unroll
            for (int o = 16; o > 0; o >>= 1) {
                #pragma unroll
                for (int r = 0; r < 4; r++) {
                    s[r]  += __shfl_xor_sync(0xffffffffu, s[r],  o);
                    ss[r] += __shfl_xor_sync(0xffffffffu, ss[r], o);
                }
            }
            if (tx == 0) {
                #pragma unroll
                for (int r = 0; r < 4; r++) {
                    __stcg(&g_part[0][b0 + r][blk], s[r]);
                    __stcg(&g_part[1][b0 + r][blk], ss[r]);
                }
            }
        }

        gsync(++nsync * NBLK);

        if (ty < 8) {
            // ---- aggregate stats (deterministic) ----
            float mean[4], rstd[4];
            #pragma unroll
            for (int r = 0; r < 4; r++) {
                int row = b0 + r;
                float4 sv = __ldcg((const float4*)&g_part[0][row][tx * 4]);
                float4 qv = __ldcg((const float4*)&g_part[1][row][tx * 4]);
                float sl = (sv.x + sv.y) + (sv.z + sv.w);
                float ql = (qv.x + qv.y) + (qv.z + qv.w);
                #pragma unroll
                for (int o = 16; o > 0; o >>= 1) {
                    sl += __shfl_xor_sync(0xffffffffu, sl, o);
                    ql += __shfl_xor_sync(0xffffffffu, ql, o);
                }
                float m = sl * (1.0f / N4);
                mean[r] = m;
                rstd[r] = rsqrtf(ql * (1.0f / N4) - m * m + EPSF);
            }

            // ---- LN + gates ----
            #pragma unroll
            for (int r = 0; r < 4; r++) {
                float v = (acc[r] - mean[r]) * rstd[r] * gam + bet;
                float a0 = __shfl_sync(0xffffffffu, v, q);        // ig
                float a1 = __shfl_sync(0xffffffffu, v, q + 8);    // fg
                float a2 = __shfl_sync(0xffffffffu, v, q + 16);   // hidden
                float a3 = __shfl_sync(0xffffffffu, v, q + 24);   // og
                if (g == 0) {
                    int b = b0 + r;
                    int i = blk * 8 + q;
                    float si = 1.0f / (1.0f + expf(-a0));
                    float sf = 1.0f / (1.0f + expf(-a1));
                    float so = 1.0f / (1.0f + expf(-a3));
                    float co = c_sm[b * 8 + q];
                    float cn = sf * co + si * tanhf(a2);
                    float h  = so * cn;
                    c_sm[b * 8 + q] = cn;
                    __stcg(&g_h[(size_t)b * OSZ + i], h);
                    out[((size_t)b * SS + t) * OSZ + i] = h;
                }
            }
        }

        gsync(++nsync * NBLK);
    }
}

// ---------------------------------------------------------------------------
// Inputs (metadata order): x, W, b, gamma, beta, init_hx, init_cx
// ---------------------------------------------------------------------------
extern "C" void kernel_launch(void* const* d_in, const int* in_sizes, int n_in,
                              void* d_out, int out_size) {
    const float* x       = (const float*)d_in[0];
    const float* W       = (const float*)d_in[1];
    const float* bias    = (const float*)d_in[2];
    const float* gamma   = (const float*)d_in[3];
    const float* beta    = (const float*)d_in[4];
    const float* init_hx = (const float*)d_in[5];
    const float* init_cx = (const float*)d_in[6];
    float* out = (float*)d_out;

    init_state<<<(BB * OSZ + 255) / 256, 256>>>(init_hx);

    split_x<<<(BB * SS * ISZ) / 256, 256>>>(x);
    split_w<<<(ISZ * N4) / 256, 256>>>(W);

    xproj_mma<<<dim3(N4 / 64, (BB * SS) / 128), 256>>>(bias);

    cudaFuncSetAttribute(lstm_persist,
                         cudaFuncAttributeMaxDynamicSharedMemorySize, 196608);
    lstm_persist<<<NBLK, NTHR, 196608>>>(W, gamma, beta, init_cx, out);
}

// round 16
// speedup vs baseline: 1.7796x; 1.4152x over previous
#include <cuda_runtime.h>
#include <cuda_bf16.h>
#include <math.h>
#include <stdint.h>

#define BB     32
#define SS     256
#define ISZ    1024
#define OSZ    1024
#define N4     4096
#define EPSF   1e-5f
#define NBLK   128
#define NTHR   512
#define CHUNK  256
#define NCH    4

// SMEM word-layout constants (uint32 units)
#define WPITCH 516                 // per-col pitch of W splits (512 + 4 pad)
#define WSPLIT (32 * WPITCH)       // one W split: 16512 words
#define HBASE  (2 * WSPLIT)        // 33024 words
#define HPITCH 132                 // per-row pitch of h chunk (128 + 4 pad)
#define HSPLIT (32 * HPITCH)       // 4224 words
#define HBUF   (2 * HSPLIT)        // 8448 words per buffer (hh+hl)
#define PPITCH 264                 // Pred row pitch (words)

typedef unsigned long long ull;

// Scratch (device globals -- no runtime allocation allowed)
__device__ float         g_xproj[BB * SS * N4];
__device__ __nv_bfloat16 g_xh[BB * SS * ISZ];
__device__ __nv_bfloat16 g_xl[BB * SS * ISZ];
__device__ __nv_bfloat16 g_wh[ISZ * N4];
__device__ __nv_bfloat16 g_wl[ISZ * N4];
__device__ uint32_t      g_hw[BB * OSZ];        // h packed: lo16=hh, hi16=hl (bf16)
__device__ float         g_part[2][BB][NBLK];
__device__ unsigned      g_bar;

// ---------------------------------------------------------------------------
__device__ __forceinline__ uint32_t pack_h(float h) {
    __nv_bfloat16 hh = __float2bfloat16(h);
    float hf = __bfloat162float(hh);
    __nv_bfloat16 hl = __float2bfloat16(h - hf);
    return (uint32_t)__bfloat16_as_ushort(hh) |
           ((uint32_t)__bfloat16_as_ushort(hl) << 16);
}

// ---------------------------------------------------------------------------
// Init: packed h from init_hx, reset barrier. Covers all 32768 h elements.
// ---------------------------------------------------------------------------
__global__ void init_state(const float* __restrict__ init_hx) {
    int j = blockIdx.x * blockDim.x + threadIdx.x;
    if (j == 0) g_bar = 0;
    if (j < BB * OSZ) g_hw[j] = pack_h(init_hx[j & (OSZ - 1)]);
}

// ---------------------------------------------------------------------------
// bf16 splits for xproj GEMM
// ---------------------------------------------------------------------------
__global__ void split_x(const float* __restrict__ x) {
    int i = blockIdx.x * blockDim.x + threadIdx.x;
    float v = x[i];
    __nv_bfloat16 hi = __float2bfloat16(v);
    g_xh[i] = hi;
    g_xl[i] = __float2bfloat16(v - __bfloat162float(hi));
}
__global__ void split_w(const float* __restrict__ W) {
    int i = blockIdx.x * blockDim.x + threadIdx.x;
    float v = W[i];
    __nv_bfloat16 hi = __float2bfloat16(v);
    g_wh[i] = hi;
    g_wl[i] = __float2bfloat16(v - __bfloat162float(hi));
}

// ---------------------------------------------------------------------------
// Tensor-core xproj (proven R14): bf16x3 fused K=3072 GEMM, 128x64 tiles.
// ---------------------------------------------------------------------------
__global__ void __launch_bounds__(256)
xproj_mma(const float* __restrict__ bias) {
    __shared__ uint32_t Aw[128 * 20];
    __shared__ uint32_t Bw[64 * 20];

    const int tid  = threadIdx.x;
    const int lane = tid & 31, wid = tid >> 5;
    const int wm   = wid >> 1;
    const int wn   = wid & 1;
    const int m0   = blockIdx.y * 128;
    const int n0   = blockIdx.x * 64;

    const uint32_t* xh_w = (const uint32_t*)g_xh;
    const uint32_t* xl_w = (const uint32_t*)g_xl;
    const uint32_t* wh_w = (const uint32_t*)g_wh;
    const uint32_t* wl_w = (const uint32_t*)g_wl;

    float d[2][4][4];
    #pragma unroll
    for (int mt = 0; mt < 2; mt++)
        #pragma unroll
        for (int nt = 0; nt < 4; nt++)
            #pragma unroll
            for (int e = 0; e < 4; e++) d[mt][nt][e] = 0.f;

    const int gr = lane >> 2;
    const int gc = lane & 3;

    for (int cc = 0; cc < 96; cc++) {
        const int seg = cc >> 5, kc = cc & 31;
        const uint32_t* As = (seg < 2) ? xh_w : xl_w;
        const uint32_t* Bs = (seg == 1) ? wl_w : wh_w;

        if (cc) __syncthreads();

        #pragma unroll
        for (int u = 0; u < 8; u++) {
            int idx = u * 256 + tid;
            int r = idx >> 4, c = idx & 15;
            Aw[r * 20 + c] = As[(size_t)(m0 + r) * 512 + kc * 16 + c];
        }
        #pragma unroll
        for (int u = 0; u < 4; u++) {
            int idx = u * 256 + tid;
            int k = idx >> 5, nw = idx & 31;
            uint32_t v = Bs[(size_t)(kc * 32 + k) * 2048 + (n0 >> 1) + nw];
            uint16_t* bh = (uint16_t*)Bw;
            bh[(2 * nw)     * 40 + k] = (uint16_t)(v & 0xffffu);
            bh[(2 * nw + 1) * 40 + k] = (uint16_t)(v >> 16);
        }
        __syncthreads();

        #pragma unroll
        for (int ks = 0; ks < 2; ks++) {
            uint32_t a[2][4];
            #pragma unroll
            for (int mt = 0; mt < 2; mt++) {
                int rb = wm * 32 + mt * 16;
                a[mt][0] = Aw[(rb + gr)     * 20 + ks * 8 + gc];
                a[mt][1] = Aw[(rb + 8 + gr) * 20 + ks * 8 + gc];
                a[mt][2] = Aw[(rb + gr)     * 20 + ks * 8 + 4 + gc];
                a[mt][3] = Aw[(rb + 8 + gr) * 20 + ks * 8 + 4 + gc];
            }
            #pragma unroll
            for (int nt = 0; nt < 4; nt++) {
                int nb = wn * 32 + nt * 8;
                uint32_t b0 = Bw[(nb + gr) * 20 + ks * 8 + gc];
                uint32_t b1 = Bw[(nb + gr) * 20 + ks * 8 + 4 + gc];
                #pragma unroll
                for (int mt = 0; mt < 2; mt++) {
                    asm("mma.sync.aligned.m16n8k16.row.col.f32.bf16.bf16.f32 "
                        "{%0,%1,%2,%3}, {%4,%5,%6,%7}, {%8,%9}, {%0,%1,%2,%3};"
                        : "+f"(d[mt][nt][0]), "+f"(d[mt][nt][1]),
                          "+f"(d[mt][nt][2]), "+f"(d[mt][nt][3])
                        : "r"(a[mt][0]), "r"(a[mt][1]), "r"(a[mt][2]), "r"(a[mt][3]),
                          "r"(b0), "r"(b1));
                }
            }
        }
    }

    #pragma unroll
    for (int mt = 0; mt < 2; mt++) {
        #pragma unroll
        for (int nt = 0; nt < 4; nt++) {
            int row = m0 + wm * 32 + mt * 16 + gr;
            int col = n0 + wn * 32 + nt * 8 + gc * 2;
            float2 bv = *(const float2*)(bias + col);
            float2 v0 = { d[mt][nt][0] + bv.x, d[mt][nt][1] + bv.y };
            float2 v1 = { d[mt][nt][2] + bv.x, d[mt][nt][3] + bv.y };
            *(float2*)(g_xproj + (size_t)row * N4 + col)       = v0;
            *(float2*)(g_xproj + (size_t)(row + 8) * N4 + col) = v1;
        }
    }
}

// ---------------------------------------------------------------------------
// Grid barrier -- atomic counter on one hot L2 line (measured best)
// ---------------------------------------------------------------------------
__device__ __forceinline__ void gsync(unsigned target) {
    __syncthreads();
    if (threadIdx.x == 0) {
        __threadfence();
        atomicAdd(&g_bar, 1u);
        while (*(volatile unsigned*)&g_bar < target) { }
        __threadfence();
    }
    __syncthreads();
}

// ---------------------------------------------------------------------------
// Persistent LSTM recurrence -- recurrent GEMM on TENSOR CORES (bf16x3).
// Block owns cols {g*1024 + blk*8 + q : tx in 0..31}.
// Warp (kq=ty&7, nh=ty>>3): M=32 (2 m16), N=16 (2 n8), k32 per chunk/segment.
// Segments: hh@whh, hh@whl, hl@whh (fp32 accum). 8-way k reduction via Pred.
// LN/stats/gates identical to the proven R15 consumer path.
// ---------------------------------------------------------------------------
__global__ void __launch_bounds__(NTHR, 1)
lstm_persist(const float* __restrict__ W,
             const float* __restrict__ gamma,
             const float* __restrict__ beta,
             const float* __restrict__ init_cx,
             float* __restrict__ out) {
    extern __shared__ uint32_t smem[];
    // [0, HBASE): W splits. [HBASE, +2*HBUF): h chunk buffers (hh/hl, x2 buf)
    uint32_t* __restrict__ Hst = smem + HBASE;
    float*    __restrict__ Pred = (float*)(smem + HBASE);   // overlay on buf 0
    __shared__ float c_sm[BB * 8];

    const int tid = threadIdx.x;
    const int tx  = tid & 31, ty = tid >> 5;
    const int kq  = ty & 7;
    const int nh  = ty >> 3;
    const int blk = blockIdx.x;
    const int g   = tx >> 3, q = tx & 7;
    const int gcol = g * OSZ + blk * 8 + q;
    const int b0  = (ty & 7) * 4;          // consumer rows (ty < 8)
    const int gr  = tx >> 2, gc = tx & 3;  // mma fragment coords

    // ---- convert W_h slice to bf16 splits in SMEM ----
    for (int idx = tid; idx < 32 * 512; idx += NTHR) {
        int c = idx & 31, w = idx >> 5;
        int col = (c >> 3) * OSZ + blk * 8 + (c & 7);
        float v0 = W[(size_t)(ISZ + 2 * w)     * N4 + col];
        float v1 = W[(size_t)(ISZ + 2 * w + 1) * N4 + col];
        __nv_bfloat16 h0 = __float2bfloat16(v0);
        __nv_bfloat16 h1 = __float2bfloat16(v1);
        __nv_bfloat16 l0 = __float2bfloat16(v0 - __bfloat162float(h0));
        __nv_bfloat16 l1 = __float2bfloat16(v1 - __bfloat162float(h1));
        smem[0 * WSPLIT + c * WPITCH + w] =
            (uint32_t)__bfloat16_as_ushort(h0) | ((uint32_t)__bfloat16_as_ushort(h1) << 16);
        smem[1 * WSPLIT + c * WPITCH + w] =
            (uint32_t)__bfloat16_as_ushort(l0) | ((uint32_t)__bfloat16_as_ushort(l1) << 16);
    }
    if (tid < BB * 8)
        c_sm[tid] = init_cx[blk * 8 + (tid & 7)];

    const float gam = gamma[gcol];
    const float bet = beta[gcol];

    // staging indices: j over 2048 uint4-units per chunk (32 rows x 64)
    int st_r[4], st_q[4];
    #pragma unroll
    for (int u = 0; u < 4; u++) {
        int j = u * NTHR + tid;
        st_r[u] = j >> 6;
        st_q[u] = j & 63;
    }
    __syncthreads();

    unsigned nsync = 0;

    float px[4] = {0.f, 0.f, 0.f, 0.f};
    if (ty < 8) {
        #pragma unroll
        for (int r = 0; r < 4; r++)
            px[r] = __ldcg(&g_xproj[((size_t)(b0 + r) * SS + 0) * N4 + gcol]);
    }

    for (int t = 0; t < SS; t++) {
        float cur[4];
        #pragma unroll
        for (int r = 0; r < 4; r++) cur[r] = px[r];
        if (ty < 8 && t + 1 < SS) {
            #pragma unroll
            for (int r = 0; r < 4; r++)
                px[r] = __ldcg(&g_xproj[((size_t)(b0 + r) * SS + t + 1) * N4 + gcol]);
        }

        // ---- stage chunk 0 (unpack packed h words into hh/hl pair words) ----
        {
            uint4 ld[4];
            #pragma unroll
            for (int u = 0; u < 4; u++)
                ld[u] = __ldcg((const uint4*)(g_hw + (size_t)st_r[u] * OSZ + st_q[u] * 4));
            #pragma unroll
            for (int u = 0; u < 4; u++) {
                uint32_t hh0 = __byte_perm(ld[u].x, ld[u].y, 0x5410);
                uint32_t hl0 = __byte_perm(ld[u].x, ld[u].y, 0x7632);
                uint32_t hh1 = __byte_perm(ld[u].z, ld[u].w, 0x5410);
                uint32_t hl1 = __byte_perm(ld[u].z, ld[u].w, 0x7632);
                int base = st_r[u] * HPITCH + st_q[u] * 2;
                *(uint2*)(Hst + 0 * HSPLIT + base) = make_uint2(hh0, hh1);
                *(uint2*)(Hst + 1 * HSPLIT + base) = make_uint2(hl0, hl1);
            }
        }
        __syncthreads();

        // ---- tensor-core GEMM over 4 chunks x 3 segments ----
        float d[2][2][4];
        #pragma unroll
        for (int mt = 0; mt < 2; mt++)
            #pragma unroll
            for (int nt = 0; nt < 2; nt++)
                #pragma unroll
                for (int e = 0; e < 4; e++) d[mt][nt][e] = 0.f;

        #pragma unroll 1
        for (int c = 0; c < NCH; c++) {
            uint4 ldn[4];
            if (c < NCH - 1) {
                const int k0n = (c + 1) * CHUNK;
                #pragma unroll
                for (int u = 0; u < 4; u++)
                    ldn[u] = __ldcg((const uint4*)(g_hw + (size_t)st_r[u] * OSZ + k0n + st_q[u] * 4));
            }

            const uint32_t* __restrict__ hb = Hst + (c & 1) * HBUF;

            #pragma unroll
            for (int seg = 0; seg < 3; seg++) {
                const uint32_t* __restrict__ As = hb + ((seg < 2) ? 0 : HSPLIT);
                const uint32_t* __restrict__ Bs = smem + ((seg == 1) ? WSPLIT : 0);
                const int bw0 = c * 128 + kq * 16;

                #pragma unroll
                for (int ks = 0; ks < 2; ks++) {
                    const int aw = kq * 16 + ks * 8;
                    uint32_t a[2][4];
                    #pragma unroll
                    for (int mt = 0; mt < 2; mt++) {
                        int rb = mt * 16;
                        a[mt][0] = As[(rb + gr)     * HPITCH + aw + gc];
                        a[mt][1] = As[(rb + 8 + gr) * HPITCH + aw + gc];
                        a[mt][2] = As[(rb + gr)     * HPITCH + aw + 4 + gc];
                        a[mt][3] = As[(rb + 8 + gr) * HPITCH + aw + 4 + gc];
                    }
                    #pragma unroll
                    for (int nt = 0; nt < 2; nt++) {
                        int nb = nh * 16 + nt * 8;
                        uint32_t b0 = Bs[(nb + gr) * WPITCH + bw0 + ks * 8 + gc];
                        uint32_t b1 = Bs[(nb + gr) * WPITCH + bw0 + ks * 8 + 4 + gc];
                        #pragma unroll
                        for (int mt = 0; mt < 2; mt++) {
                            asm("mma.sync.aligned.m16n8k16.row.col.f32.bf16.bf16.f32 "
                                "{%0,%1,%2,%3}, {%4,%5,%6,%7}, {%8,%9}, {%0,%1,%2,%3};"
                                : "+f"(d[mt][nt][0]), "+f"(d[mt][nt][1]),
                                  "+f"(d[mt][nt][2]), "+f"(d[mt][nt][3])
                                : "r"(a[mt][0]), "r"(a[mt][1]), "r"(a[mt][2]), "r"(a[mt][3]),
                                  "r"(b0), "r"(b1));
                        }
                    }
                }
            }

            if (c < NCH - 1) {
                __syncthreads();   // all reads of next buffer's region done (overlay safety)
                uint32_t* __restrict__ hn = Hst + ((c + 1) & 1) * HBUF;
                #pragma unroll
                for (int u = 0; u < 4; u++) {
                    uint32_t hh0 = __byte_perm(ldn[u].x, ldn[u].y, 0x5410);
                    uint32_t hl0 = __byte_perm(ldn[u].x, ldn[u].y, 0x7632);
                    uint32_t hh1 = __byte_perm(ldn[u].z, ldn[u].w, 0x5410);
                    uint32_t hl1 = __byte_perm(ldn[u].z, ldn[u].w, 0x7632);
                    int base = st_r[u] * HPITCH + st_q[u] * 2;
                    *(uint2*)(hn + 0 * HSPLIT + base) = make_uint2(hh0, hh1);
                    *(uint2*)(hn + 1 * HSPLIT + base) = make_uint2(hl0, hl1);
                }
                __syncthreads();
            }
        }
        __syncthreads();   // GEMM reads done before Pred overlay writes

        // ---- write k-partials to Pred[row][kq][col] (pitch 264) ----
        #pragma unroll
        for (int mt = 0; mt < 2; mt++) {
            #pragma unroll
            for (int nt = 0; nt < 2; nt++) {
                int row = mt * 16 + gr;
                int col = nh * 16 + nt * 8 + gc * 2;
                *(float2*)&Pred[row * PPITCH + kq * 32 + col] =
                    make_float2(d[mt][nt][0], d[mt][nt][1]);
                *(float2*)&Pred[(row + 8) * PPITCH + kq * 32 + col] =
                    make_float2(d[mt][nt][2], d[mt][nt][3]);
            }
        }
        __syncthreads();

        float acc[4] = {0.f, 0.f, 0.f, 0.f};
        if (ty < 8) {
            #pragma unroll
            for (int r = 0; r < 4; r++) {
                const int row = b0 + r;
                float sum = 0.f;
                #pragma unroll
                for (int w = 0; w < 8; w++)
                    sum += Pred[row * PPITCH + w * 32 + tx];
                acc[r] = sum + cur[r];
            }

            float s[4], ss[4];
            #pragma unroll
            for (int r = 0; r < 4; r++) { s[r] = acc[r]; ss[r] = acc[r] * acc[r]; }
            #pragma unroll
            for (int o = 16; o > 0; o >>= 1) {
                #pragma unroll
                for (int r = 0; r < 4; r++) {
                    s[r]  += __shfl_xor_sync(0xffffffffu, s[r],  o);
                    ss[r] += __shfl_xor_sync(0xffffffffu, ss[r], o);
                }
            }
            if (tx == 0) {
                #pragma unroll
                for (int r = 0; r < 4; r++) {
                    __stcg(&g_part[0][b0 + r][blk], s[r]);
                    __stcg(&g_part[1][b0 + r][blk], ss[r]);
                }
            }
        }

        gsync(++nsync * NBLK);

        if (ty < 8) {
            float mean[4], rstd[4];
            #pragma unroll
            for (int r = 0; r < 4; r++) {
                int row = b0 + r;
                float4 sv = __ldcg((const float4*)&g_part[0][row][tx * 4]);
                float4 qv = __ldcg((const float4*)&g_part[1][row][tx * 4]);
                float sl = (sv.x + sv.y) + (sv.z + sv.w);
                float ql = (qv.x + qv.y) + (qv.z + qv.w);
                #pragma unroll
                for (int o = 16; o > 0; o >>= 1) {
                    sl += __shfl_xor_sync(0xffffffffu, sl, o);
                    ql += __shfl_xor_sync(0xffffffffu, ql, o);
                }
                float m = sl * (1.0f / N4);
                mean[r] = m;
                rstd[r] = rsqrtf(ql * (1.0f / N4) - m * m + EPSF);
            }

            #pragma unroll
            for (int r = 0; r < 4; r++) {
                float v = (acc[r] - mean[r]) * rstd[r] * gam + bet;
                float a0 = __shfl_sync(0xffffffffu, v, q);
                float a1 = __shfl_sync(0xffffffffu, v, q + 8);
                float a2 = __shfl_sync(0xffffffffu, v, q + 16);
                float a3 = __shfl_sync(0xffffffffu, v, q + 24);
                if (g == 0) {
                    int b = b0 + r;
                    int i = blk * 8 + q;
                    float si = 1.0f / (1.0f + expf(-a0));
                    float sf = 1.0f / (1.0f + expf(-a1));
                    float so = 1.0f / (1.0f + expf(-a3));
                    float co = c_sm[b * 8 + q];
                    float cn = sf * co + si * tanhf(a2);
                    float h  = so * cn;
                    c_sm[b * 8 + q] = cn;
                    __stcg(&g_hw[(size_t)b * OSZ + i], pack_h(h));
                    out[((size_t)b * SS + t) * OSZ + i] = h;
                }
            }
        }

        gsync(++nsync * NBLK);
    }
}

// ---------------------------------------------------------------------------
// Inputs (metadata order): x, W, b, gamma, beta, init_hx, init_cx
// ---------------------------------------------------------------------------
extern "C" void kernel_launch(void* const* d_in, const int* in_sizes, int n_in,
                              void* d_out, int out_size) {
    const float* x       = (const float*)d_in[0];
    const float* W       = (const float*)d_in[1];
    const float* bias    = (const float*)d_in[2];
    const float* gamma   = (const float*)d_in[3];
    const float* beta    = (const float*)d_in[4];
    const float* init_hx = (const float*)d_in[5];
    const float* init_cx = (const float*)d_in[6];
    float* out = (float*)d_out;

    init_state<<<(BB * OSZ + 255) / 256, 256>>>(init_hx);

    split_x<<<(BB * SS * ISZ) / 256, 256>>>(x);
    split_w<<<(ISZ * N4) / 256, 256>>>(W);

    xproj_mma<<<dim3(N4 / 64, (BB * SS) / 128), 256>>>(bias);

    // dynamic smem: (HBASE + 2*HBUF) words = (33024 + 16896) * 4 = 199680 B
    cudaFuncSetAttribute(lstm_persist,
                         cudaFuncAttributeMaxDynamicSharedMemorySize, 199680);
    lstm_persist<<<NBLK, NTHR, 199680>>>(W, gamma, beta, init_cx, out);
}